// round 16
// baseline (speedup 1.0000x reference)
#include <cuda_runtime.h>
#include <cuda_bf16.h>
#include <mma.h>
#include <cstdint>
#include <math.h>

// ============================================================================
// Dimensions:  B=8, N=2048, D=1028 -> pad 1152, H=4112 -> pad 4224.
// M = B*N = 16384. N-dim tiled 256-wide; ragged N handled by +128 zero slack
// rows on B-side operands + store guards. Padded regions are exact zeros.
// ============================================================================
#define MROWS  16384
#define NPOS   2048
#define NBATCH 8
#define DREAL  1028
#define DP     1152
#define HREAL  4112
#define HP     4224

#if defined(__CUDA_ARCH_FEAT_SM103_ALL) || defined(__CUDA_ARCH_FEAT_SM100_ALL) || defined(__CUDA_ARCH_SPECIFIC__)
#define USE_TCGEN05 1
#else
#define USE_TCGEN05 0
#endif

// ---- scratch (device globals; zero-initialized; no runtime allocation) ----
__device__ __nv_bfloat16 g_xb  [(size_t)MROWS * DP];
__device__ __nv_bfloat16 g_q   [(size_t)MROWS * DP];
__device__ __nv_bfloat16 g_k   [(size_t)MROWS * DP];
__device__ __nv_bfloat16 g_v   [(size_t)MROWS * DP];
__device__ __nv_bfloat16 g_vt  [((size_t)NBATCH * DP + 128) * NPOS];
__device__ __nv_bfloat16 g_attn[(size_t)MROWS * DP];
__device__ __nv_bfloat16 g_h   [(size_t)MROWS * HP];
__device__ __nv_bfloat16 g_S   [(size_t)NBATCH * NPOS * NPOS];
__device__ __nv_bfloat16 g_P   [(size_t)NBATCH * NPOS * NPOS];
__device__ __nv_bfloat16 g_Wq  [((size_t)DP + 128) * DP];
__device__ __nv_bfloat16 g_Wk  [((size_t)DP + 128) * DP];
__device__ __nv_bfloat16 g_Wv  [((size_t)DP + 128) * DP];
__device__ __nv_bfloat16 g_We  [((size_t)HP + 128) * DP];
__device__ __nv_bfloat16 g_Wo  [((size_t)DP + 128) * HP];

// ============================================================================
// PTX helpers
// ============================================================================
__device__ __forceinline__ uint32_t smem_u32(const void* p) {
    uint32_t a;
    asm("{ .reg .u64 t; cvta.to.shared.u64 t, %1; cvt.u32.u64 %0, t; }"
        : "=r"(a) : "l"(p));
    return a;
}
#define CP_ASYNC16(dst, src) \
    asm volatile("cp.async.cg.shared.global [%0], [%1], 16;" \
                 :: "r"(dst), "l"(src) : "memory")
#define CP_COMMIT() asm volatile("cp.async.commit_group;" ::: "memory")
#define CP_WAIT(n)  asm volatile("cp.async.wait_group %0;" :: "n"(n) : "memory")

#if USE_TCGEN05
__device__ __forceinline__ uint32_t elect_one() {
    uint32_t p;
    asm volatile("{\n\t.reg .pred p;\n\telect.sync _|p, 0xFFFFFFFF;\n\t"
                 "selp.b32 %0, 1, 0, p;\n\t}" : "=r"(p));
    return p;
}
#define MBAR_INIT(addr, cnt) \
    asm volatile("mbarrier.init.shared.b64 [%0], %1;" :: "r"(addr), "r"(cnt) : "memory")
#define MBAR_ARRIVE(addr) \
    asm volatile("mbarrier.arrive.shared.b64 _, [%0];" :: "r"(addr) : "memory")
#define MBAR_WAIT(addr, par) do {                                              \
    uint32_t _m = (addr), _p = (par), _d;                                      \
    asm volatile("{\n\t.reg .pred p;\n\t"                                      \
        "mbarrier.try_wait.parity.acquire.cta.shared::cta.b64 p, [%1], %2;\n\t"\
        "selp.b32 %0, 1, 0, p;\n\t}" : "=r"(_d) : "r"(_m), "r"(_p) : "memory");\
    if (!_d) {                                                                 \
        asm volatile("{\n\t.reg .pred P1;\n\t"                                 \
        "W_%=:\n\t"                                                            \
        "mbarrier.try_wait.parity.acquire.cta.shared::cta.b64 P1, [%0], %1, 0x989680;\n\t" \
        "@P1 bra.uni D_%=;\n\t"                                                \
        "bra.uni W_%=;\n\t"                                                    \
        "D_%=:\n\t}" :: "r"(_m), "r"(_p) : "memory");                          \
    }                                                                          \
} while (0)
#define TC_ALLOC(smem_addr, n) \
    asm volatile("tcgen05.alloc.cta_group::1.sync.aligned.shared::cta.b32 [%0], %1;" \
                 :: "r"(smem_addr), "r"((uint32_t)(n)) : "memory")
#define TC_RELINQ() \
    asm volatile("tcgen05.relinquish_alloc_permit.cta_group::1.sync.aligned;")
#define TC_DEALLOC(tmem, n) \
    asm volatile("tcgen05.dealloc.cta_group::1.sync.aligned.b32 %0, %1;" \
                 :: "r"(tmem), "r"((uint32_t)(n)))
#define TC_COMMIT(mbar) \
    asm volatile("tcgen05.commit.cta_group::1.mbarrier::arrive::one.shared::cluster.b64 [%0];" \
                 :: "r"(mbar) : "memory")
#define TC_FENCE_AFTER()  asm volatile("tcgen05.fence::after_thread_sync;" ::: "memory")
#define TC_FENCE_BEFORE() asm volatile("tcgen05.fence::before_thread_sync;" ::: "memory")
#define FENCE_ASYNC_SHARED() asm volatile("fence.proxy.async.shared::cta;" ::: "memory")
#define TC_WAIT_LD() asm volatile("tcgen05.wait::ld.sync.aligned;" ::: "memory")

#define TC_LD_X32(r, addr)                                                     \
    asm volatile("tcgen05.ld.sync.aligned.32x32b.x32.b32 "                     \
        "{%0, %1, %2, %3, %4, %5, %6, %7, %8, %9, %10, %11, %12, %13, %14, %15,"\
        " %16, %17, %18, %19, %20, %21, %22, %23, %24, %25, %26, %27, %28, %29, %30, %31}, [%32];" \
        : "=r"((r)[0]), "=r"((r)[1]), "=r"((r)[2]), "=r"((r)[3]),              \
          "=r"((r)[4]), "=r"((r)[5]), "=r"((r)[6]), "=r"((r)[7]),              \
          "=r"((r)[8]), "=r"((r)[9]), "=r"((r)[10]), "=r"((r)[11]),            \
          "=r"((r)[12]), "=r"((r)[13]), "=r"((r)[14]), "=r"((r)[15]),          \
          "=r"((r)[16]), "=r"((r)[17]), "=r"((r)[18]), "=r"((r)[19]),          \
          "=r"((r)[20]), "=r"((r)[21]), "=r"((r)[22]), "=r"((r)[23]),          \
          "=r"((r)[24]), "=r"((r)[25]), "=r"((r)[26]), "=r"((r)[27]),          \
          "=r"((r)[28]), "=r"((r)[29]), "=r"((r)[30]), "=r"((r)[31])           \
        : "r"(addr))

// bf16 SS MMA, cta_group::1, kind::f16, fp32 accum
__device__ __forceinline__ void mma_ss(uint32_t d, uint64_t ad, uint64_t bd,
                                       uint32_t idesc, uint32_t en) {
    asm volatile(
        "{\n\t.reg .pred p;\n\tsetp.ne.u32 p, %5, 0;\n\t"
        "tcgen05.mma.cta_group::1.kind::f16 [%0], %1, %2, %3, {%4, %4, %4, %4}, p;\n\t}"
        :: "r"(d), "l"(ad), "l"(bd), "r"(idesc), "r"(0u), "r"(en) : "memory");
}
// K-major SW128 descriptor (validated: LBO=1, SBO=64, layout=2, version=1)
__device__ __forceinline__ uint64_t mk_desc(uint32_t addr) {
    return ((uint64_t)2 << 61) | ((uint64_t)1 << 46) | ((uint64_t)64 << 32) |
           ((uint64_t)1 << 16) | (uint64_t)((addr >> 4) & 0x3FFF);
}
// idesc: F32 accum, BF16 A/B, M=128, N=128 (validated)
#define TC_IDESC 0x8200490u
#endif  // USE_TCGEN05

// ============================================================================
// GEMM:  C[M,N] = A[M,K] * B[N,K]^T  (bf16 row-major, fp32 acc)
// CTA tile 256x256, 256 threads.
//   sm_103a : WARP-SPECIALIZED tcgen05. Warps 1-7 = cp.async producers
//             (full[s] mbar, count 224, writer-side proxy fence before arrive).
//             Warp 0 = MMA consumer (empty[s] via tcgen05.commit, count 1).
//             3 stages x 64KB, no __syncthreads in mainloop.
//   generic : WMMA fallback, two sequential 128-col halves, 2-stage cp.async
// EPI: 0 fp32 | 1 bf16((v+b)*alpha) | 2 bf16(gelu(v+b)) | 3 fp32(v+b+x) | 4 bf16(v)
// ============================================================================
#define NSTG 3
#define PLAG 2
#define STG_BYTES 65536
#define SMEM_BYTES (NSTG * STG_BYTES + 1024)

template <int EPI>
__global__ __launch_bounds__(256)
void tc_gemm(const __nv_bfloat16* __restrict__ Ag,
             const __nv_bfloat16* __restrict__ Bg,
             void* __restrict__ Cv,
             int K, int lda, int ldb, int ldc, int Nstore,
             const float* __restrict__ bias, int nbias, float alpha,
             const float* __restrict__ xres,
             size_t sA, size_t sB, size_t sC) {
    extern __shared__ char dsm_raw[];
    const int tid = threadIdx.x;
    const int wid = tid >> 5;
    const int z = blockIdx.z;
    Ag += z * sA;
    Bg += z * sB;
    const int m0 = blockIdx.y * 256;
    const int n0 = blockIdx.x * 256;

#if USE_TCGEN05
    // ------------------------------------------------------------------
    // tcgen05 warp-specialized body
    // ------------------------------------------------------------------
    char* smem = (char*)(((uintptr_t)dsm_raw + 1023) & ~(uintptr_t)1023);
    __shared__ __align__(16) unsigned long long mbar_full[NSTG];
    __shared__ __align__(16) unsigned long long mbar_empty[NSTG];
    __shared__ __align__(16) unsigned long long mbar_done[1];
    __shared__ uint32_t tmem_store[1];

    const uint32_t smb = smem_u32(smem);
    uint32_t slotA[NSTG], slotB[NSTG], mbF[NSTG], mbE[NSTG];
    uint64_t dA[NSTG][2], dB[NSTG][2];
#pragma unroll
    for (int s = 0; s < NSTG; s++) {
        slotA[s] = smb + s * STG_BYTES;        // A: 256 rows x 128B (2x16KB)
        slotB[s] = slotA[s] + 32768;           // B: 256 rows x 128B (2x16KB)
        dA[s][0] = mk_desc(slotA[s]);
        dA[s][1] = mk_desc(slotA[s] + 16384);
        dB[s][0] = mk_desc(slotB[s]);
        dB[s][1] = mk_desc(slotB[s] + 16384);
        mbF[s] = smem_u32(&mbar_full[s]);
        mbE[s] = smem_u32(&mbar_empty[s]);
    }
    const uint32_t mbD = smem_u32(&mbar_done[0]);
    const uint32_t tps = smem_u32(&tmem_store[0]);

    if (wid == 0) { TC_ALLOC(tps, 512); TC_RELINQ(); }
    if (tid == 0) {
#pragma unroll
        for (int s = 0; s < NSTG; s++) {
            MBAR_INIT(mbF[s], 224);            // one arrive per producer thread
            MBAR_INIT(mbE[s], 1);              // tcgen05.commit
        }
        MBAR_INIT(mbD, 1);
    }
    __syncthreads();
    uint32_t tmem;
    asm volatile("ld.shared.b32 %0, [%1];" : "=r"(tmem) : "r"(tps));

    const int nc = K >> 6;                     // BK = 64
    const size_t ldab = (size_t)lda * 2, ldbb = (size_t)ldb * 2;
    const char* Abase = (const char*)(Ag + (size_t)m0 * lda);
    const char* Bbase = (const char*)(Bg + (size_t)n0 * ldb);

    if (wid == 0) {
        // ---------------- MMA consumer warp ----------------
        int phF[NSTG];
#pragma unroll
        for (int s = 0; s < NSTG; s++) phF[s] = 0;
        for (int cc = 0; cc < nc; cc++) {
            const int s = cc % NSTG;
            MBAR_WAIT(mbF[s], phF[s]);
            phF[s] ^= 1;
            if (elect_one()) {
#pragma unroll
                for (int st = 0; st < 4; st++) {       // 4 K-steps of 16
#pragma unroll
                    for (int h = 0; h < 2; h++) {      // M-halves
#pragma unroll
                        for (int nh = 0; nh < 2; nh++) // N-halves
                            mma_ss(tmem + h * 256 + nh * 128,
                                   dA[s][h] + st * 2, dB[s][nh] + st * 2,
                                   TC_IDESC, (cc > 0 || st > 0) ? 1u : 0u);
                    }
                }
                TC_COMMIT(mbE[s]);
            }
        }
        if (elect_one()) TC_COMMIT(mbD);       // tracks ALL prior MMAs
    } else {
        // ---------------- producer warps (224 threads) ----------------
        const int ptid = tid - 32;
        int phE[NSTG];
#pragma unroll
        for (int s = 0; s < NSTG; s++) phE[s] = 0;
        for (int c = 0; c < nc; c++) {
            const int s = c % NSTG;
            if (c >= NSTG) { MBAR_WAIT(mbE[s], phE[s]); phE[s] ^= 1; }
            const char* Ab = Abase + (size_t)c * 128;  // 64 bf16 = 128B
            const char* Bb = Bbase + (size_t)c * 128;
            const uint32_t sa = slotA[s], sb = slotB[s];
            for (int cid = ptid; cid < 2048; cid += 224) {   // A
                int r = cid >> 3, cb = (cid & 7) << 4;
                uint32_t off = ((r & 127) << 7) + cb;
                uint32_t sw = off ^ ((off >> 3) & 0x70);
                CP_ASYNC16(sa + ((r >> 7) << 14) + sw, Ab + (size_t)r * ldab + cb);
            }
            for (int cid = ptid; cid < 2048; cid += 224) {   // B
                int r = cid >> 3, cb = (cid & 7) << 4;
                uint32_t off = ((r & 127) << 7) + cb;
                uint32_t sw = off ^ ((off >> 3) & 0x70);
                CP_ASYNC16(sb + ((r >> 7) << 14) + sw, Bb + (size_t)r * ldbb + cb);
            }
            CP_COMMIT();
            if (c >= PLAG) {
                CP_WAIT(PLAG);                 // this thread's group c-PLAG done
                FENCE_ASYNC_SHARED();          // writer-side generic->async
                MBAR_ARRIVE(mbF[(c - PLAG) % NSTG]);
            }
        }
        // tail: flush remaining PLAG groups
        CP_WAIT(0);
        FENCE_ASYNC_SHARED();
        for (int r = (nc > PLAG ? nc - PLAG : 0); r < nc; r++)
            MBAR_ARRIVE(mbF[r % NSTG]);
    }

    __syncthreads();
    MBAR_WAIT(mbD, 0);
    TC_FENCE_AFTER();

    // ---- epilogue: wg = M-half (TMEM col base), sp = 32-row subpartition ----
    {
        const int wg = wid >> 2, sp = wid & 3, lane = tid & 31;
        const int gm = m0 + wg * 128 + sp * 32 + lane;
        float* Cf = (float*)Cv + z * sC;
        __nv_bfloat16* Cb = (__nv_bfloat16*)Cv + z * sC;
#pragma unroll
        for (int b = 0; b < 8; b++) {
            const int gn0 = n0 + b * 32;
            if (gn0 >= Nstore) continue;       // uniform across warp
            uint32_t regs[32];
            TC_LD_X32(regs, tmem + wg * 256 + b * 32);
            TC_WAIT_LD();
            float v[32];
#pragma unroll
            for (int j = 0; j < 32; j++) {
                float t = __uint_as_float(regs[j]);
                const int gn = gn0 + j;
                if (EPI == 1) {
                    float bb = (gn < nbias) ? bias[gn] : 0.0f;
                    t = (t + bb) * alpha;
                } else if (EPI == 2) {
                    float bb = (gn < nbias) ? bias[gn] : 0.0f;
                    float u = t + bb;
                    t = 0.5f * u * (1.0f + erff(u * 0.70710678118654752f));
                } else if (EPI == 3) {
                    float bb = (gn < nbias) ? bias[gn] : 0.0f;
                    t = t + bb;                // residual added below
                }
                v[j] = t;
            }
            const bool full = (gn0 + 32 <= Nstore);
            if (EPI == 0 || EPI == 3) {
                if (full) {
                    if (EPI == 3) {
                        const float4* xr = (const float4*)(xres + (size_t)gm * DREAL + gn0);
                        float4* dst = (float4*)(Cf + (size_t)gm * ldc + gn0);
#pragma unroll
                        for (int q4 = 0; q4 < 8; q4++) {
                            float4 xv = xr[q4];
                            dst[q4] = make_float4(v[q4*4+0] + xv.x, v[q4*4+1] + xv.y,
                                                  v[q4*4+2] + xv.z, v[q4*4+3] + xv.w);
                        }
                    } else {
                        float4* dst = (float4*)(Cf + (size_t)gm * ldc + gn0);
#pragma unroll
                        for (int q4 = 0; q4 < 8; q4++)
                            dst[q4] = make_float4(v[q4*4], v[q4*4+1], v[q4*4+2], v[q4*4+3]);
                    }
                } else {
#pragma unroll
                    for (int j = 0; j < 32; j++) {
                        int gn = gn0 + j;
                        if (gn < Nstore) {
                            float t = v[j];
                            if (EPI == 3) t += xres[(size_t)gm * DREAL + gn];
                            Cf[(size_t)gm * ldc + gn] = t;
                        }
                    }
                }
            } else {                           // bf16 outputs
                if (full) {
                    uint32_t pk[16];
#pragma unroll
                    for (int p = 0; p < 16; p++) {
                        __nv_bfloat162 h2 = __floats2bfloat162_rn(v[2*p], v[2*p+1]);
                        pk[p] = *(uint32_t*)&h2;
                    }
                    uint4* dst = (uint4*)(Cb + (size_t)gm * ldc + gn0);
#pragma unroll
                    for (int q4 = 0; q4 < 4; q4++)
                        dst[q4] = make_uint4(pk[q4*4], pk[q4*4+1], pk[q4*4+2], pk[q4*4+3]);
                } else {
#pragma unroll
                    for (int j = 0; j < 32; j++) {
                        int gn = gn0 + j;
                        if (gn < Nstore)
                            Cb[(size_t)gm * ldc + gn] = __float2bfloat16(v[j]);
                    }
                }
            }
        }
        TC_FENCE_BEFORE();
    }
    __syncthreads();
    if (wid == 0) TC_DEALLOC(tmem, 512);

#else
    // ------------------------------------------------------------------
    // WMMA fallback: two sequential 128-col halves of the 256-wide tile
    // ------------------------------------------------------------------
    using namespace nvcuda;
    const int lane = tid & 31;
    const uint32_t smb = smem_u32(dsm_raw);
    __nv_bfloat16* AsP[2] = {(__nv_bfloat16*)dsm_raw,
                             (__nv_bfloat16*)(dsm_raw + 30720)};
    __nv_bfloat16* BsP[2] = {(__nv_bfloat16*)(dsm_raw + 20480),
                             (__nv_bfloat16*)(dsm_raw + 30720 + 20480)};
    float* stage = (float*)(dsm_raw + 61440);

    const int wm = (wid & 3) * 64;
    const int wn = (wid >> 2) * 64;
    const size_t ldab = (size_t)lda * 2, ldbb = (size_t)ldb * 2;
    const int nc = K >> 5;

    for (int half = 0; half < 2; half++) {
        const int nh0 = blockIdx.x * 256 + half * 128;
        const char* Abase = (const char*)(Ag + (size_t)m0 * lda);
        const char* Bbase = (const char*)(Bg + (size_t)nh0 * ldb);

        wmma::fragment<wmma::accumulator, 16, 16, 16, float> acc[4][4];
#pragma unroll
        for (int i = 0; i < 4; i++)
#pragma unroll
            for (int j = 0; j < 4; j++) wmma::fill_fragment(acc[i][j], 0.0f);

        auto issue = [&](int cc, int s) {
            const uint32_t sa = smb + s * 30720;
            const uint32_t sb = sa + 20480;
            const char* Ab = Abase + (size_t)cc * 64;
            const char* Bb = Bbase + (size_t)cc * 64;
#pragma unroll
            for (int i = 0; i < 4; i++) {
                int cid = tid + i * 256;
                int r = cid >> 2, cb = (cid & 3) << 4;
                CP_ASYNC16(sa + r * 80 + cb, Ab + (size_t)r * ldab + cb);
            }
#pragma unroll
            for (int i = 0; i < 2; i++) {
                int cid = tid + i * 256;
                int r = cid >> 2, cb = (cid & 3) << 4;
                CP_ASYNC16(sb + r * 80 + cb, Bb + (size_t)r * ldbb + cb);
            }
        };

        issue(0, 0);
        CP_COMMIT();
        for (int c = 0; c < nc; c++) {
            if (c + 1 < nc) issue(c + 1, (c + 1) & 1);
            CP_COMMIT();
            CP_WAIT(1);
            __syncthreads();
            const __nv_bfloat16* As = AsP[c & 1];
            const __nv_bfloat16* Bs = BsP[c & 1];
#pragma unroll
            for (int kk = 0; kk < 32; kk += 16) {
                wmma::fragment<wmma::matrix_a, 16, 16, 16, __nv_bfloat16, wmma::row_major> af[4];
                wmma::fragment<wmma::matrix_b, 16, 16, 16, __nv_bfloat16, wmma::col_major> bf[4];
#pragma unroll
                for (int i = 0; i < 4; i++)
                    wmma::load_matrix_sync(af[i], As + (size_t)(wm + i * 16) * 40 + kk, 40);
#pragma unroll
                for (int j = 0; j < 4; j++)
                    wmma::load_matrix_sync(bf[j], Bs + (size_t)(wn + j * 16) * 40 + kk, 40);
#pragma unroll
                for (int i = 0; i < 4; i++)
#pragma unroll
                    for (int j = 0; j < 4; j++)
                        wmma::mma_sync(acc[i][j], af[i], bf[j], acc[i][j]);
            }
            __syncthreads();
        }

        float* st = stage + wid * 256;
        float* Cf = (float*)Cv + z * sC;
        __nv_bfloat16* Cb = (__nv_bfloat16*)Cv + z * sC;
#pragma unroll
        for (int i = 0; i < 4; i++) {
#pragma unroll
            for (int j = 0; j < 4; j++) {
                wmma::store_matrix_sync(st, acc[i][j], 16, wmma::mem_row_major);
                __syncwarp();
#pragma unroll
                for (int e = lane; e < 256; e += 32) {
                    int r = e >> 4, cx = e & 15;
                    int gm = m0 + wm + i * 16 + r;
                    int gn = nh0 + wn + j * 16 + cx;
                    if (gn < Nstore) {
                        float val = st[e];
                        if (EPI == 0) {
                            Cf[(size_t)gm * ldc + gn] = val;
                        } else if (EPI == 1) {
                            float b = (gn < nbias) ? bias[gn] : 0.0f;
                            Cb[(size_t)gm * ldc + gn] = __float2bfloat16((val + b) * alpha);
                        } else if (EPI == 2) {
                            float b = (gn < nbias) ? bias[gn] : 0.0f;
                            float t = val + b;
                            float g = 0.5f * t * (1.0f + erff(t * 0.70710678118654752f));
                            Cb[(size_t)gm * ldc + gn] = __float2bfloat16(g);
                        } else if (EPI == 3) {
                            float b = (gn < nbias) ? bias[gn] : 0.0f;
                            Cf[(size_t)gm * ldc + gn] =
                                val + b + xres[(size_t)gm * DREAL + gn];
                        } else {
                            Cb[(size_t)gm * ldc + gn] = __float2bfloat16(val);
                        }
                    }
                }
                __syncwarp();
            }
        }
        __syncthreads();
    }
#endif  // USE_TCGEN05
}

// ============================================================================
// Fused prep: all fp32->bf16 pads in ONE launch (flat index, 6-job table)
// ============================================================================
struct PrepArgs {
    const float* src[6];
    __nv_bfloat16* dst[6];
    int R[6], C[6], Cp[6];
    long long base[7];
};

__global__ __launch_bounds__(256)
void prep_kernel(PrepArgs a) {
    long long idx = (long long)blockIdx.x * 256 + threadIdx.x;
    if (idx >= a.base[6]) return;
    int j = 0;
#pragma unroll
    for (int t = 1; t < 6; t++)
        if (idx >= a.base[t]) j = t;
    long long loc = idx - a.base[j];
    int r = (int)(loc / a.Cp[j]);
    int c = (int)(loc % a.Cp[j]);
    float v = (r < a.R[j] && c < a.C[j]) ? a.src[j][(size_t)r * a.C[j] + c] : 0.0f;
    a.dst[j][loc] = __float2bfloat16(v);
}

// ============================================================================
// per-batch transpose: v[z][n][d] (DP wide) -> vt[z][d][n] (NPOS wide)
// ============================================================================
__global__ __launch_bounds__(256)
void transpose_kernel(const __nv_bfloat16* __restrict__ v,
                      __nv_bfloat16* __restrict__ vt) {
    __shared__ __nv_bfloat16 t[32][33];
    const int z = blockIdx.z;
    const int nb = blockIdx.x * 32, db = blockIdx.y * 32;
    const int tx = threadIdx.x & 31, ty = threadIdx.x >> 5;
    const __nv_bfloat16* vsrc = v + (size_t)z * NPOS * DP;
    __nv_bfloat16* vdst = vt + (size_t)z * DP * NPOS;
#pragma unroll
    for (int i = 0; i < 4; i++)
        t[ty + i * 8][tx] = vsrc[(size_t)(nb + ty + i * 8) * DP + db + tx];
    __syncthreads();
#pragma unroll
    for (int i = 0; i < 4; i++)
        vdst[(size_t)(db + ty + i * 8) * NPOS + nb + tx] = t[tx][ty + i * 8];
}

// ============================================================================
// Row softmax: S bf16 [rows, 2048] -> P bf16
// ============================================================================
__global__ __launch_bounds__(256)
void softmax_kernel(const __nv_bfloat16* __restrict__ S,
                    __nv_bfloat16* __restrict__ P) {
    const size_t row = blockIdx.x;
    const __nv_bfloat16* s = S + row * (size_t)NPOS;
    __nv_bfloat16* p = P + row * (size_t)NPOS;
    const int tid = threadIdx.x, wid = tid >> 5, lane = tid & 31;
    float v[8], mx = -1e30f;
#pragma unroll
    for (int i = 0; i < 8; i++) {
        v[i] = __bfloat162float(s[tid + i * 256]);
        mx = fmaxf(mx, v[i]);
    }
    __shared__ float rm[8], rs[8];
#pragma unroll
    for (int o = 16; o > 0; o >>= 1) mx = fmaxf(mx, __shfl_xor_sync(~0u, mx, o));
    if (lane == 0) rm[wid] = mx;
    __syncthreads();
    float bm = rm[0];
#pragma unroll
    for (int i = 1; i < 8; i++) bm = fmaxf(bm, rm[i]);
    float sum = 0.0f;
#pragma unroll
    for (int i = 0; i < 8; i++) { v[i] = __expf(v[i] - bm); sum += v[i]; }
#pragma unroll
    for (int o = 16; o > 0; o >>= 1) sum += __shfl_xor_sync(~0u, sum, o);
    if (lane == 0) rs[wid] = sum;
    __syncthreads();
    float tot = 0.0f;
#pragma unroll
    for (int i = 0; i < 8; i++) tot += rs[i];
    float inv = 1.0f / tot;
#pragma unroll
    for (int i = 0; i < 8; i++) p[tid + i * 256] = __float2bfloat16(v[i] * inv);
}

// ============================================================================
// launch — prep(1), gemm-q(2), gemm-k(3), gemm-v(4), scores(5), ...
// ============================================================================
extern "C" void kernel_launch(void* const* d_in, const int* in_sizes, int n_in,
                              void* d_out, int out_size) {
    const float* x  = (const float*)d_in[0];
    const float* Wq = (const float*)d_in[1];
    const float* bq = (const float*)d_in[2];
    const float* Wk = (const float*)d_in[3];
    const float* bk = (const float*)d_in[4];
    const float* Wv = (const float*)d_in[5];
    const float* bv = (const float*)d_in[6];
    const float* We = (const float*)d_in[7];
    const float* be = (const float*)d_in[8];
    const float* Wo = (const float*)d_in[9];
    const float* bo = (const float*)d_in[10];

    void *p_xb, *p_q, *p_k, *p_v, *p_vt, *p_attn, *p_h, *p_S, *p_P;
    void *p_Wq, *p_Wk, *p_Wv, *p_We, *p_Wo;
    cudaGetSymbolAddress(&p_xb, g_xb);
    cudaGetSymbolAddress(&p_q, g_q);
    cudaGetSymbolAddress(&p_k, g_k);
    cudaGetSymbolAddress(&p_v, g_v);
    cudaGetSymbolAddress(&p_vt, g_vt);
    cudaGetSymbolAddress(&p_attn, g_attn);
    cudaGetSymbolAddress(&p_h, g_h);
    cudaGetSymbolAddress(&p_S, g_S);
    cudaGetSymbolAddress(&p_P, g_P);
    cudaGetSymbolAddress(&p_Wq, g_Wq);
    cudaGetSymbolAddress(&p_Wk, g_Wk);
    cudaGetSymbolAddress(&p_Wv, g_Wv);
    cudaGetSymbolAddress(&p_We, g_We);
    cudaGetSymbolAddress(&p_Wo, g_Wo);

    cudaFuncSetAttribute(tc_gemm<0>, cudaFuncAttributeMaxDynamicSharedMemorySize, SMEM_BYTES);
    cudaFuncSetAttribute(tc_gemm<1>, cudaFuncAttributeMaxDynamicSharedMemorySize, SMEM_BYTES);
    cudaFuncSetAttribute(tc_gemm<2>, cudaFuncAttributeMaxDynamicSharedMemorySize, SMEM_BYTES);
    cudaFuncSetAttribute(tc_gemm<3>, cudaFuncAttributeMaxDynamicSharedMemorySize, SMEM_BYTES);
    cudaFuncSetAttribute(tc_gemm<4>, cudaFuncAttributeMaxDynamicSharedMemorySize, SMEM_BYTES);

    const float qscale = 1.0f / sqrtf((float)DREAL);
    dim3 blk(256);

    // launch 1: fused prep (all pads; slack rows written as zeros)
    {
        PrepArgs a;
        a.src[0] = x;  a.dst[0] = (__nv_bfloat16*)p_xb;
        a.R[0] = MROWS; a.C[0] = DREAL; a.Cp[0] = DP;
        long long n0 = (long long)MROWS * DP;
        a.src[1] = Wq; a.dst[1] = (__nv_bfloat16*)p_Wq;
        a.R[1] = DREAL; a.C[1] = DREAL; a.Cp[1] = DP;
        long long n1 = (long long)(DP + 128) * DP;
        a.src[2] = Wk; a.dst[2] = (__nv_bfloat16*)p_Wk;
        a.R[2] = DREAL; a.C[2] = DREAL; a.Cp[2] = DP;
        a.src[3] = Wv; a.dst[3] = (__nv_bfloat16*)p_Wv;
        a.R[3] = DREAL; a.C[3] = DREAL; a.Cp[3] = DP;
        a.src[4] = We; a.dst[4] = (__nv_bfloat16*)p_We;
        a.R[4] = HREAL; a.C[4] = DREAL; a.Cp[4] = DP;
        long long n4 = (long long)(HP + 128) * DP;
        a.src[5] = Wo; a.dst[5] = (__nv_bfloat16*)p_Wo;
        a.R[5] = DREAL; a.C[5] = HREAL; a.Cp[5] = HP;
        long long n5 = (long long)(DP + 128) * HP;
        a.base[0] = 0;
        a.base[1] = n0;
        a.base[2] = n0 + n1;
        a.base[3] = n0 + 2 * n1;
        a.base[4] = n0 + 3 * n1;
        a.base[5] = n0 + 3 * n1 + n4;
        a.base[6] = n0 + 3 * n1 + n4 + n5;
        int blocks = (int)((a.base[6] + 255) / 256);
        prep_kernel<<<blocks, 256>>>(a);
    }

    // launches 2-4: q/k/v projections (N=1152 -> 5 tiles of 256)
    {
        dim3 grid(5, MROWS / 256, 1);
        tc_gemm<1><<<grid, blk, SMEM_BYTES>>>(
            (const __nv_bfloat16*)p_xb, (const __nv_bfloat16*)p_Wq, p_q,
            DP, DP, DP, DP, DP, bq, DREAL, qscale, nullptr, 0, 0, 0);
        tc_gemm<1><<<grid, blk, SMEM_BYTES>>>(
            (const __nv_bfloat16*)p_xb, (const __nv_bfloat16*)p_Wk, p_k,
            DP, DP, DP, DP, DP, bk, DREAL, 1.0f, nullptr, 0, 0, 0);
        tc_gemm<1><<<grid, blk, SMEM_BYTES>>>(
            (const __nv_bfloat16*)p_xb, (const __nv_bfloat16*)p_Wv, p_v,
            DP, DP, DP, DP, DP, bv, DREAL, 1.0f, nullptr, 0, 0, 0);
    }

    // launch 5: scores, S = q @ k^T (scale folded into q), bf16 out
    {
        dim3 grid(NPOS / 256, NPOS / 256, NBATCH);  // (8,8,8)
        tc_gemm<4><<<grid, blk, SMEM_BYTES>>>(
            (const __nv_bfloat16*)p_q, (const __nv_bfloat16*)p_k, p_S,
            DP, DP, DP, NPOS, NPOS, nullptr, 0, 1.0f, nullptr,
            (size_t)NPOS * DP, (size_t)NPOS * DP, (size_t)NPOS * NPOS);
    }

    // launch 6: transpose V per batch (needs only v)
    {
        dim3 grid(NPOS / 32, DP / 32, NBATCH);
        transpose_kernel<<<grid, blk>>>((const __nv_bfloat16*)p_v,
                                        (__nv_bfloat16*)p_vt);
    }

    // launch 7: softmax rows
    softmax_kernel<<<NBATCH * NPOS, 256>>>((const __nv_bfloat16*)p_S,
                                           (__nv_bfloat16*)p_P);

    // attn = P @ Vt^T  (N=1152 -> 5 tiles; vt has slack rows)
    {
        dim3 grid(5, NPOS / 256, NBATCH);
        tc_gemm<4><<<grid, blk, SMEM_BYTES>>>(
            (const __nv_bfloat16*)p_P, (const __nv_bfloat16*)p_vt, p_attn,
            NPOS, NPOS, NPOS, DP, DP, nullptr, 0, 1.0f, nullptr,
            (size_t)NPOS * NPOS, (size_t)DP * NPOS, (size_t)NPOS * DP);
    }

    // h = gelu(attn @ We^T + be)  (N=4224 -> 17 tiles; We has slack rows)
    {
        dim3 grid(17, MROWS / 256, 1);
        tc_gemm<2><<<grid, blk, SMEM_BYTES>>>(
            (const __nv_bfloat16*)p_attn, (const __nv_bfloat16*)p_We, p_h,
            DP, DP, DP, HP, HP, be, HREAL, 1.0f, nullptr, 0, 0, 0);
    }

    // out = h @ Wo^T + bo + x  (fp32; N=1028 -> 5 tiles; Wo has slack rows)
    {
        dim3 grid(5, MROWS / 256, 1);
        tc_gemm<3><<<grid, blk, SMEM_BYTES>>>(
            (const __nv_bfloat16*)p_h, (const __nv_bfloat16*)p_Wo, d_out,
            HP, HP, HP, DREAL, DREAL, bo, DREAL, 1.0f, x, 0, 0, 0);
    }
}

// round 17
// speedup vs baseline: 1.5066x; 1.5066x over previous
#include <cuda_runtime.h>
#include <cuda_bf16.h>
#include <mma.h>
#include <cstdint>
#include <math.h>

// ============================================================================
// Dimensions:  B=8, N=2048, D=1028 -> pad 1152 (9*128), H=4112 -> pad 4224
// (33*128). M = B*N = 16384. 128-wide N tiles: all GEMMs tile exactly.
// Padded regions are exact zeros.
// ============================================================================
#define MROWS  16384
#define NPOS   2048
#define NBATCH 8
#define DREAL  1028
#define DP     1152
#define HREAL  4112
#define HP     4224

#if defined(__CUDA_ARCH_FEAT_SM103_ALL) || defined(__CUDA_ARCH_FEAT_SM100_ALL) || defined(__CUDA_ARCH_SPECIFIC__)
#define USE_TCGEN05 1
#else
#define USE_TCGEN05 0
#endif

// ---- scratch (device globals; zero-initialized; no runtime allocation) ----
__device__ __nv_bfloat16 g_xb  [(size_t)MROWS * DP];
__device__ __nv_bfloat16 g_q   [(size_t)MROWS * DP];
__device__ __nv_bfloat16 g_k   [(size_t)MROWS * DP];
__device__ __nv_bfloat16 g_v   [(size_t)MROWS * DP];
__device__ __nv_bfloat16 g_vt  [((size_t)NBATCH * DP + 128) * NPOS];
__device__ __nv_bfloat16 g_attn[(size_t)MROWS * DP];
__device__ __nv_bfloat16 g_h   [(size_t)MROWS * HP];
__device__ __nv_bfloat16 g_S   [(size_t)NBATCH * NPOS * NPOS];
__device__ __nv_bfloat16 g_P   [(size_t)NBATCH * NPOS * NPOS];
__device__ __nv_bfloat16 g_Wq  [((size_t)DP + 128) * DP];
__device__ __nv_bfloat16 g_Wk  [((size_t)DP + 128) * DP];
__device__ __nv_bfloat16 g_Wv  [((size_t)DP + 128) * DP];
__device__ __nv_bfloat16 g_We  [((size_t)HP + 128) * DP];
__device__ __nv_bfloat16 g_Wo  [((size_t)DP + 128) * HP];

// ============================================================================
// PTX helpers
// ============================================================================
__device__ __forceinline__ uint32_t smem_u32(const void* p) {
    uint32_t a;
    asm("{ .reg .u64 t; cvta.to.shared.u64 t, %1; cvt.u32.u64 %0, t; }"
        : "=r"(a) : "l"(p));
    return a;
}
#define CP_ASYNC16(dst, src) \
    asm volatile("cp.async.cg.shared.global [%0], [%1], 16;" \
                 :: "r"(dst), "l"(src) : "memory")
#define CP_COMMIT() asm volatile("cp.async.commit_group;" ::: "memory")
#define CP_WAIT(n)  asm volatile("cp.async.wait_group %0;" :: "n"(n) : "memory")

#if USE_TCGEN05
__device__ __forceinline__ uint32_t elect_one() {
    uint32_t p;
    asm volatile("{\n\t.reg .pred p;\n\telect.sync _|p, 0xFFFFFFFF;\n\t"
                 "selp.b32 %0, 1, 0, p;\n\t}" : "=r"(p));
    return p;
}
#define MBAR_INIT(addr, cnt) \
    asm volatile("mbarrier.init.shared.b64 [%0], %1;" :: "r"(addr), "r"(cnt) : "memory")
#define MBAR_WAIT(addr, par) do {                                              \
    uint32_t _m = (addr), _p = (par), _d;                                      \
    asm volatile("{\n\t.reg .pred p;\n\t"                                      \
        "mbarrier.try_wait.parity.acquire.cta.shared::cta.b64 p, [%1], %2;\n\t"\
        "selp.b32 %0, 1, 0, p;\n\t}" : "=r"(_d) : "r"(_m), "r"(_p) : "memory");\
    if (!_d) {                                                                 \
        asm volatile("{\n\t.reg .pred P1;\n\t"                                 \
        "W_%=:\n\t"                                                            \
        "mbarrier.try_wait.parity.acquire.cta.shared::cta.b64 P1, [%0], %1, 0x989680;\n\t" \
        "@P1 bra.uni D_%=;\n\t"                                                \
        "bra.uni W_%=;\n\t"                                                    \
        "D_%=:\n\t}" :: "r"(_m), "r"(_p) : "memory");                          \
    }                                                                          \
} while (0)
#define TC_ALLOC(smem_addr, n) \
    asm volatile("tcgen05.alloc.cta_group::1.sync.aligned.shared::cta.b32 [%0], %1;" \
                 :: "r"(smem_addr), "r"((uint32_t)(n)) : "memory")
#define TC_RELINQ() \
    asm volatile("tcgen05.relinquish_alloc_permit.cta_group::1.sync.aligned;")
#define TC_DEALLOC(tmem, n) \
    asm volatile("tcgen05.dealloc.cta_group::1.sync.aligned.b32 %0, %1;" \
                 :: "r"(tmem), "r"((uint32_t)(n)))
#define TC_COMMIT(mbar) \
    asm volatile("tcgen05.commit.cta_group::1.mbarrier::arrive::one.shared::cluster.b64 [%0];" \
                 :: "r"(mbar) : "memory")
#define TC_FENCE_AFTER()  asm volatile("tcgen05.fence::after_thread_sync;" ::: "memory")
#define TC_FENCE_BEFORE() asm volatile("tcgen05.fence::before_thread_sync;" ::: "memory")
#define FENCE_ASYNC_SHARED() asm volatile("fence.proxy.async.shared::cta;" ::: "memory")
#define TC_WAIT_LD() asm volatile("tcgen05.wait::ld.sync.aligned;" ::: "memory")

#define TC_LD_X32(r, addr)                                                     \
    asm volatile("tcgen05.ld.sync.aligned.32x32b.x32.b32 "                     \
        "{%0, %1, %2, %3, %4, %5, %6, %7, %8, %9, %10, %11, %12, %13, %14, %15,"\
        " %16, %17, %18, %19, %20, %21, %22, %23, %24, %25, %26, %27, %28, %29, %30, %31}, [%32];" \
        : "=r"((r)[0]), "=r"((r)[1]), "=r"((r)[2]), "=r"((r)[3]),              \
          "=r"((r)[4]), "=r"((r)[5]), "=r"((r)[6]), "=r"((r)[7]),              \
          "=r"((r)[8]), "=r"((r)[9]), "=r"((r)[10]), "=r"((r)[11]),            \
          "=r"((r)[12]), "=r"((r)[13]), "=r"((r)[14]), "=r"((r)[15]),          \
          "=r"((r)[16]), "=r"((r)[17]), "=r"((r)[18]), "=r"((r)[19]),          \
          "=r"((r)[20]), "=r"((r)[21]), "=r"((r)[22]), "=r"((r)[23]),          \
          "=r"((r)[24]), "=r"((r)[25]), "=r"((r)[26]), "=r"((r)[27]),          \
          "=r"((r)[28]), "=r"((r)[29]), "=r"((r)[30]), "=r"((r)[31])           \
        : "r"(addr))

// bf16 SS MMA, cta_group::1, kind::f16, fp32 accum
__device__ __forceinline__ void mma_ss(uint32_t d, uint64_t ad, uint64_t bd,
                                       uint32_t idesc, uint32_t en) {
    asm volatile(
        "{\n\t.reg .pred p;\n\tsetp.ne.u32 p, %5, 0;\n\t"
        "tcgen05.mma.cta_group::1.kind::f16 [%0], %1, %2, %3, {%4, %4, %4, %4}, p;\n\t}"
        :: "r"(d), "l"(ad), "l"(bd), "r"(idesc), "r"(0u), "r"(en) : "memory");
}
// K-major SW128 descriptor (validated: LBO=1, SBO=64, layout=2, version=1)
__device__ __forceinline__ uint64_t mk_desc(uint32_t addr) {
    return ((uint64_t)2 << 61) | ((uint64_t)1 << 46) | ((uint64_t)64 << 32) |
           ((uint64_t)1 << 16) | (uint64_t)((addr >> 4) & 0x3FFF);
}
// idesc: F32 accum, BF16 A/B, M=128, N=128 (validated)
#define TC_IDESC 0x8200490u
#endif  // USE_TCGEN05

// ============================================================================
// GEMM:  C[M,N] = A[M,K] * B[N,K]^T  (bf16 row-major, fp32 acc)
// CTA tile 256x128, 256 threads, TWO CTAs PER SM (96KB smem each, TMEM 256
// cols each -> 512 total). Cross-CTA overlap on the shared tensor pipe hides
// the shallow (NSTG=2, lag=1) per-CTA pipeline's latency exposure.
//   sm_103a : tcgen05 lockstep, BK=64, 2-stage cp.async (SW128, 48KB/stage)
//   generic : WMMA fallback, 2-stage cp.async, 8 warps of 64x64
// EPI: 0 fp32 | 1 bf16((v+b)*alpha) | 2 bf16(gelu(v+b)) | 3 fp32(v+b+x) | 4 bf16(v)
// ============================================================================
#define NSTG 2
#define MMALAG 1
#define STG_BYTES 49152
#define SMEM_BYTES (NSTG * STG_BYTES + 1024)   // 99328 -> 2 CTAs/SM

template <int EPI>
__global__ __launch_bounds__(256)
void tc_gemm(const __nv_bfloat16* __restrict__ Ag,
             const __nv_bfloat16* __restrict__ Bg,
             void* __restrict__ Cv,
             int K, int lda, int ldb, int ldc, int Nstore,
             const float* __restrict__ bias, int nbias, float alpha,
             const float* __restrict__ xres,
             size_t sA, size_t sB, size_t sC) {
    extern __shared__ char dsm_raw[];
    const int tid = threadIdx.x;
    const int wid = tid >> 5;
    const int z = blockIdx.z;
    Ag += z * sA;
    Bg += z * sB;
    const int m0 = blockIdx.y * 256;
    const int n0 = blockIdx.x * 128;

#if USE_TCGEN05
    // ------------------------------------------------------------------
    // tcgen05 body — 2-stage cp.async pipeline, lag 1, 2 CTAs/SM
    // ------------------------------------------------------------------
    char* smem = (char*)(((uintptr_t)dsm_raw + 1023) & ~(uintptr_t)1023);
    __shared__ __align__(16) unsigned long long mbar_store[NSTG];
    __shared__ uint32_t tmem_store[1];

    const uint32_t smb = smem_u32(smem);
    uint32_t slotA[NSTG], slotB[NSTG], mb[NSTG];
    uint64_t dAh[NSTG][2], dBv[NSTG];
#pragma unroll
    for (int s = 0; s < NSTG; s++) {
        slotA[s] = smb + s * STG_BYTES;        // A: 256 rows x 128B (2x16KB)
        slotB[s] = slotA[s] + 32768;           // B: 128 rows x 128B (16KB)
        dAh[s][0] = mk_desc(slotA[s]);
        dAh[s][1] = mk_desc(slotA[s] + 16384);
        dBv[s] = mk_desc(slotB[s]);
        mb[s] = smem_u32(&mbar_store[s]);
    }
    const uint32_t tps = smem_u32(&tmem_store[0]);

    if (wid == 0) { TC_ALLOC(tps, 256); TC_RELINQ(); }
    if (tid == 0) {
#pragma unroll
        for (int s = 0; s < NSTG; s++) MBAR_INIT(mb[s], 1);
    }
    __syncthreads();
    uint32_t tmem;
    asm volatile("ld.shared.b32 %0, [%1];" : "=r"(tmem) : "r"(tps));

    const int nc = K >> 6;                     // BK = 64
    const size_t ldab = (size_t)lda * 2, ldbb = (size_t)ldb * 2;
    const char* Abase = (const char*)(Ag + (size_t)m0 * lda);
    const char* Bbase = (const char*)(Bg + (size_t)n0 * ldb);
    int phase[NSTG];
#pragma unroll
    for (int s = 0; s < NSTG; s++) phase[s] = 0;

    for (int c = 0; c < nc + MMALAG; c++) {
        if (c < nc) {
            const int s = c & 1;
            if (c >= NSTG) { MBAR_WAIT(mb[s], phase[s]); phase[s] ^= 1; }
            const char* Ab = Abase + (size_t)c * 128;  // 64 bf16 = 128B
            const char* Bb = Bbase + (size_t)c * 128;
            const uint32_t sa = slotA[s], sb = slotB[s];
#pragma unroll
            for (int i = 0; i < 8; i++) {      // A: 256 rows x 128B
                int cid = tid + i * 256;
                int r = cid >> 3, cb = (cid & 7) << 4;
                uint32_t off = ((r & 127) << 7) + cb;
                uint32_t sw = off ^ ((off >> 3) & 0x70);
                CP_ASYNC16(sa + ((r >> 7) << 14) + sw, Ab + (size_t)r * ldab + cb);
            }
#pragma unroll
            for (int i = 0; i < 4; i++) {      // B: 128 rows x 128B
                int cid = tid + i * 256;
                int r = cid >> 3, cb = (cid & 7) << 4;
                uint32_t off = (r << 7) + cb;
                uint32_t sw = off ^ ((off >> 3) & 0x70);
                CP_ASYNC16(sb + sw, Bb + (size_t)r * ldbb + cb);
            }
        }
        CP_COMMIT();                           // 1 group / iter (may be empty)
        if (c >= MMALAG) {
            CP_WAIT(MMALAG);                   // group c-1 complete
            FENCE_ASYNC_SHARED();
            __syncthreads();
            const int cc = c - MMALAG, s2 = cc & 1;
            if (wid == 0) {
                if (elect_one()) {
#pragma unroll
                    for (int st = 0; st < 4; st++) {   // 4 K-steps of 16
#pragma unroll
                        for (int h = 0; h < 2; h++) {  // 2 M-halves
                            mma_ss(tmem + h * 128, dAh[s2][h] + st * 2,
                                   dBv[s2] + st * 2, TC_IDESC,
                                   (cc > 0 || st > 0) ? 1u : 0u);
                        }
                    }
                    TC_COMMIT(mb[s2]);
                }
            }
        }
    }
#pragma unroll
    for (int s = 0; s < NSTG; s++) MBAR_WAIT(mb[s], phase[s]);
    TC_FENCE_AFTER();

    // ---- epilogue: wg = M-half (TMEM col base), sp = 32-row subpartition ----
    {
        const int wg = wid >> 2, sp = wid & 3, lane = tid & 31;
        const int gm = m0 + wg * 128 + sp * 32 + lane;
        float* Cf = (float*)Cv + z * sC;
        __nv_bfloat16* Cb = (__nv_bfloat16*)Cv + z * sC;
#pragma unroll
        for (int b = 0; b < 4; b++) {
            const int gn0 = n0 + b * 32;
            if (gn0 >= Nstore) continue;       // uniform across warp
            uint32_t regs[32];
            TC_LD_X32(regs, tmem + wg * 128 + b * 32);
            TC_WAIT_LD();
            float v[32];
#pragma unroll
            for (int j = 0; j < 32; j++) {
                float t = __uint_as_float(regs[j]);
                const int gn = gn0 + j;
                if (EPI == 1) {
                    float bb = (gn < nbias) ? bias[gn] : 0.0f;
                    t = (t + bb) * alpha;
                } else if (EPI == 2) {
                    float bb = (gn < nbias) ? bias[gn] : 0.0f;
                    float u = t + bb;
                    t = 0.5f * u * (1.0f + erff(u * 0.70710678118654752f));
                } else if (EPI == 3) {
                    float bb = (gn < nbias) ? bias[gn] : 0.0f;
                    t = t + bb;                // residual added below
                }
                v[j] = t;
            }
            const bool full = (gn0 + 32 <= Nstore);
            if (EPI == 0 || EPI == 3) {
                if (full) {
                    if (EPI == 3) {
                        const float4* xr = (const float4*)(xres + (size_t)gm * DREAL + gn0);
                        float4* dst = (float4*)(Cf + (size_t)gm * ldc + gn0);
#pragma unroll
                        for (int q4 = 0; q4 < 8; q4++) {
                            float4 xv = xr[q4];
                            dst[q4] = make_float4(v[q4*4+0] + xv.x, v[q4*4+1] + xv.y,
                                                  v[q4*4+2] + xv.z, v[q4*4+3] + xv.w);
                        }
                    } else {
                        float4* dst = (float4*)(Cf + (size_t)gm * ldc + gn0);
#pragma unroll
                        for (int q4 = 0; q4 < 8; q4++)
                            dst[q4] = make_float4(v[q4*4], v[q4*4+1], v[q4*4+2], v[q4*4+3]);
                    }
                } else {
#pragma unroll
                    for (int j = 0; j < 32; j++) {
                        int gn = gn0 + j;
                        if (gn < Nstore) {
                            float t = v[j];
                            if (EPI == 3) t += xres[(size_t)gm * DREAL + gn];
                            Cf[(size_t)gm * ldc + gn] = t;
                        }
                    }
                }
            } else {                           // bf16 outputs
                if (full) {
                    uint32_t pk[16];
#pragma unroll
                    for (int p = 0; p < 16; p++) {
                        __nv_bfloat162 h2 = __floats2bfloat162_rn(v[2*p], v[2*p+1]);
                        pk[p] = *(uint32_t*)&h2;
                    }
                    uint4* dst = (uint4*)(Cb + (size_t)gm * ldc + gn0);
#pragma unroll
                    for (int q4 = 0; q4 < 4; q4++)
                        dst[q4] = make_uint4(pk[q4*4], pk[q4*4+1], pk[q4*4+2], pk[q4*4+3]);
                } else {
#pragma unroll
                    for (int j = 0; j < 32; j++) {
                        int gn = gn0 + j;
                        if (gn < Nstore)
                            Cb[(size_t)gm * ldc + gn] = __float2bfloat16(v[j]);
                    }
                }
            }
        }
        TC_FENCE_BEFORE();
    }
    __syncthreads();
    if (wid == 0) TC_DEALLOC(tmem, 256);

#else
    // ------------------------------------------------------------------
    // WMMA fallback body (compute_103 pass) — 2-stage cp.async, BK=32
    // ------------------------------------------------------------------
    using namespace nvcuda;
    const int lane = tid & 31;
    const uint32_t smb = smem_u32(dsm_raw);
    __nv_bfloat16* AsP[2] = {(__nv_bfloat16*)dsm_raw,
                             (__nv_bfloat16*)(dsm_raw + 30720)};
    __nv_bfloat16* BsP[2] = {(__nv_bfloat16*)(dsm_raw + 20480),
                             (__nv_bfloat16*)(dsm_raw + 30720 + 20480)};
    float* stage = (float*)(dsm_raw + 61440);

    const int wm = (wid & 3) * 64;
    const int wn = (wid >> 2) * 64;
    const size_t ldab = (size_t)lda * 2, ldbb = (size_t)ldb * 2;
    const char* Abase = (const char*)(Ag + (size_t)m0 * lda);
    const char* Bbase = (const char*)(Bg + (size_t)n0 * ldb);

    wmma::fragment<wmma::accumulator, 16, 16, 16, float> acc[4][4];
#pragma unroll
    for (int i = 0; i < 4; i++)
#pragma unroll
        for (int j = 0; j < 4; j++) wmma::fill_fragment(acc[i][j], 0.0f);

    const int nc = K >> 5;
    auto issue = [&](int cc, int s) {
        const uint32_t sa = smb + s * 30720;
        const uint32_t sb = sa + 20480;
        const char* Ab = Abase + (size_t)cc * 64;
        const char* Bb = Bbase + (size_t)cc * 64;
#pragma unroll
        for (int i = 0; i < 4; i++) {
            int cid = tid + i * 256;
            int r = cid >> 2, cb = (cid & 3) << 4;
            CP_ASYNC16(sa + r * 80 + cb, Ab + (size_t)r * ldab + cb);
        }
#pragma unroll
        for (int i = 0; i < 2; i++) {
            int cid = tid + i * 256;
            int r = cid >> 2, cb = (cid & 3) << 4;
            CP_ASYNC16(sb + r * 80 + cb, Bb + (size_t)r * ldbb + cb);
        }
    };

    issue(0, 0);
    CP_COMMIT();
    for (int c = 0; c < nc; c++) {
        if (c + 1 < nc) issue(c + 1, (c + 1) & 1);
        CP_COMMIT();
        CP_WAIT(1);
        __syncthreads();
        const __nv_bfloat16* As = AsP[c & 1];
        const __nv_bfloat16* Bs = BsP[c & 1];
#pragma unroll
        for (int kk = 0; kk < 32; kk += 16) {
            wmma::fragment<wmma::matrix_a, 16, 16, 16, __nv_bfloat16, wmma::row_major> af[4];
            wmma::fragment<wmma::matrix_b, 16, 16, 16, __nv_bfloat16, wmma::col_major> bf[4];
#pragma unroll
            for (int i = 0; i < 4; i++)
                wmma::load_matrix_sync(af[i], As + (size_t)(wm + i * 16) * 40 + kk, 40);
#pragma unroll
            for (int j = 0; j < 4; j++)
                wmma::load_matrix_sync(bf[j], Bs + (size_t)(wn + j * 16) * 40 + kk, 40);
#pragma unroll
            for (int i = 0; i < 4; i++)
#pragma unroll
                for (int j = 0; j < 4; j++)
                    wmma::mma_sync(acc[i][j], af[i], bf[j], acc[i][j]);
        }
        __syncthreads();
    }

    float* st = stage + wid * 256;
    float* Cf = (float*)Cv + z * sC;
    __nv_bfloat16* Cb = (__nv_bfloat16*)Cv + z * sC;
#pragma unroll
    for (int i = 0; i < 4; i++) {
#pragma unroll
        for (int j = 0; j < 4; j++) {
            wmma::store_matrix_sync(st, acc[i][j], 16, wmma::mem_row_major);
            __syncwarp();
#pragma unroll
            for (int e = lane; e < 256; e += 32) {
                int r = e >> 4, cx = e & 15;
                int gm = m0 + wm + i * 16 + r;
                int gn = n0 + wn + j * 16 + cx;
                if (gn < Nstore) {
                    float val = st[e];
                    if (EPI == 0) {
                        Cf[(size_t)gm * ldc + gn] = val;
                    } else if (EPI == 1) {
                        float b = (gn < nbias) ? bias[gn] : 0.0f;
                        Cb[(size_t)gm * ldc + gn] = __float2bfloat16((val + b) * alpha);
                    } else if (EPI == 2) {
                        float b = (gn < nbias) ? bias[gn] : 0.0f;
                        float t = val + b;
                        float g = 0.5f * t * (1.0f + erff(t * 0.70710678118654752f));
                        Cb[(size_t)gm * ldc + gn] = __float2bfloat16(g);
                    } else if (EPI == 3) {
                        float b = (gn < nbias) ? bias[gn] : 0.0f;
                        Cf[(size_t)gm * ldc + gn] =
                            val + b + xres[(size_t)gm * DREAL + gn];
                    } else {
                        Cb[(size_t)gm * ldc + gn] = __float2bfloat16(val);
                    }
                }
            }
            __syncwarp();
        }
    }
#endif  // USE_TCGEN05
}

// ============================================================================
// Fused prep: all fp32->bf16 pads in ONE launch (flat index, 6-job table)
// ============================================================================
struct PrepArgs {
    const float* src[6];
    __nv_bfloat16* dst[6];
    int R[6], C[6], Cp[6];
    long long base[7];
};

__global__ __launch_bounds__(256)
void prep_kernel(PrepArgs a) {
    long long idx = (long long)blockIdx.x * 256 + threadIdx.x;
    if (idx >= a.base[6]) return;
    int j = 0;
#pragma unroll
    for (int t = 1; t < 6; t++)
        if (idx >= a.base[t]) j = t;
    long long loc = idx - a.base[j];
    int r = (int)(loc / a.Cp[j]);
    int c = (int)(loc % a.Cp[j]);
    float v = (r < a.R[j] && c < a.C[j]) ? a.src[j][(size_t)r * a.C[j] + c] : 0.0f;
    a.dst[j][loc] = __float2bfloat16(v);
}

// ============================================================================
// per-batch transpose: v[z][n][d] (DP wide) -> vt[z][d][n] (NPOS wide)
// ============================================================================
__global__ __launch_bounds__(256)
void transpose_kernel(const __nv_bfloat16* __restrict__ v,
                      __nv_bfloat16* __restrict__ vt) {
    __shared__ __nv_bfloat16 t[32][33];
    const int z = blockIdx.z;
    const int nb = blockIdx.x * 32, db = blockIdx.y * 32;
    const int tx = threadIdx.x & 31, ty = threadIdx.x >> 5;
    const __nv_bfloat16* vsrc = v + (size_t)z * NPOS * DP;
    __nv_bfloat16* vdst = vt + (size_t)z * DP * NPOS;
#pragma unroll
    for (int i = 0; i < 4; i++)
        t[ty + i * 8][tx] = vsrc[(size_t)(nb + ty + i * 8) * DP + db + tx];
    __syncthreads();
#pragma unroll
    for (int i = 0; i < 4; i++)
        vdst[(size_t)(db + ty + i * 8) * NPOS + nb + tx] = t[tx][ty + i * 8];
}

// ============================================================================
// Row softmax: S bf16 [rows, 2048] -> P bf16
// ============================================================================
__global__ __launch_bounds__(256)
void softmax_kernel(const __nv_bfloat16* __restrict__ S,
                    __nv_bfloat16* __restrict__ P) {
    const size_t row = blockIdx.x;
    const __nv_bfloat16* s = S + row * (size_t)NPOS;
    __nv_bfloat16* p = P + row * (size_t)NPOS;
    const int tid = threadIdx.x, wid = tid >> 5, lane = tid & 31;
    float v[8], mx = -1e30f;
#pragma unroll
    for (int i = 0; i < 8; i++) {
        v[i] = __bfloat162float(s[tid + i * 256]);
        mx = fmaxf(mx, v[i]);
    }
    __shared__ float rm[8], rs[8];
#pragma unroll
    for (int o = 16; o > 0; o >>= 1) mx = fmaxf(mx, __shfl_xor_sync(~0u, mx, o));
    if (lane == 0) rm[wid] = mx;
    __syncthreads();
    float bm = rm[0];
#pragma unroll
    for (int i = 1; i < 8; i++) bm = fmaxf(bm, rm[i]);
    float sum = 0.0f;
#pragma unroll
    for (int i = 0; i < 8; i++) { v[i] = __expf(v[i] - bm); sum += v[i]; }
#pragma unroll
    for (int o = 16; o > 0; o >>= 1) sum += __shfl_xor_sync(~0u, sum, o);
    if (lane == 0) rs[wid] = sum;
    __syncthreads();
    float tot = 0.0f;
#pragma unroll
    for (int i = 0; i < 8; i++) tot += rs[i];
    float inv = 1.0f / tot;
#pragma unroll
    for (int i = 0; i < 8; i++) p[tid + i * 256] = __float2bfloat16(v[i] * inv);
}

// ============================================================================
// launch — prep(1), gemm-q(2), gemm-k(3), gemm-v(4), scores(5), ...
// ============================================================================
extern "C" void kernel_launch(void* const* d_in, const int* in_sizes, int n_in,
                              void* d_out, int out_size) {
    const float* x  = (const float*)d_in[0];
    const float* Wq = (const float*)d_in[1];
    const float* bq = (const float*)d_in[2];
    const float* Wk = (const float*)d_in[3];
    const float* bk = (const float*)d_in[4];
    const float* Wv = (const float*)d_in[5];
    const float* bv = (const float*)d_in[6];
    const float* We = (const float*)d_in[7];
    const float* be = (const float*)d_in[8];
    const float* Wo = (const float*)d_in[9];
    const float* bo = (const float*)d_in[10];

    void *p_xb, *p_q, *p_k, *p_v, *p_vt, *p_attn, *p_h, *p_S, *p_P;
    void *p_Wq, *p_Wk, *p_Wv, *p_We, *p_Wo;
    cudaGetSymbolAddress(&p_xb, g_xb);
    cudaGetSymbolAddress(&p_q, g_q);
    cudaGetSymbolAddress(&p_k, g_k);
    cudaGetSymbolAddress(&p_v, g_v);
    cudaGetSymbolAddress(&p_vt, g_vt);
    cudaGetSymbolAddress(&p_attn, g_attn);
    cudaGetSymbolAddress(&p_h, g_h);
    cudaGetSymbolAddress(&p_S, g_S);
    cudaGetSymbolAddress(&p_P, g_P);
    cudaGetSymbolAddress(&p_Wq, g_Wq);
    cudaGetSymbolAddress(&p_Wk, g_Wk);
    cudaGetSymbolAddress(&p_Wv, g_Wv);
    cudaGetSymbolAddress(&p_We, g_We);
    cudaGetSymbolAddress(&p_Wo, g_Wo);

    cudaFuncSetAttribute(tc_gemm<0>, cudaFuncAttributeMaxDynamicSharedMemorySize, SMEM_BYTES);
    cudaFuncSetAttribute(tc_gemm<1>, cudaFuncAttributeMaxDynamicSharedMemorySize, SMEM_BYTES);
    cudaFuncSetAttribute(tc_gemm<2>, cudaFuncAttributeMaxDynamicSharedMemorySize, SMEM_BYTES);
    cudaFuncSetAttribute(tc_gemm<3>, cudaFuncAttributeMaxDynamicSharedMemorySize, SMEM_BYTES);
    cudaFuncSetAttribute(tc_gemm<4>, cudaFuncAttributeMaxDynamicSharedMemorySize, SMEM_BYTES);

    const float qscale = 1.0f / sqrtf((float)DREAL);
    dim3 blk(256);

    // launch 1: fused prep (all pads; slack rows written as zeros)
    {
        PrepArgs a;
        a.src[0] = x;  a.dst[0] = (__nv_bfloat16*)p_xb;
        a.R[0] = MROWS; a.C[0] = DREAL; a.Cp[0] = DP;
        long long n0 = (long long)MROWS * DP;
        a.src[1] = Wq; a.dst[1] = (__nv_bfloat16*)p_Wq;
        a.R[1] = DREAL; a.C[1] = DREAL; a.Cp[1] = DP;
        long long n1 = (long long)(DP + 128) * DP;
        a.src[2] = Wk; a.dst[2] = (__nv_bfloat16*)p_Wk;
        a.R[2] = DREAL; a.C[2] = DREAL; a.Cp[2] = DP;
        a.src[3] = Wv; a.dst[3] = (__nv_bfloat16*)p_Wv;
        a.R[3] = DREAL; a.C[3] = DREAL; a.Cp[3] = DP;
        a.src[4] = We; a.dst[4] = (__nv_bfloat16*)p_We;
        a.R[4] = HREAL; a.C[4] = DREAL; a.Cp[4] = DP;
        long long n4 = (long long)(HP + 128) * DP;
        a.src[5] = Wo; a.dst[5] = (__nv_bfloat16*)p_Wo;
        a.R[5] = DREAL; a.C[5] = HREAL; a.Cp[5] = HP;
        long long n5 = (long long)(DP + 128) * HP;
        a.base[0] = 0;
        a.base[1] = n0;
        a.base[2] = n0 + n1;
        a.base[3] = n0 + 2 * n1;
        a.base[4] = n0 + 3 * n1;
        a.base[5] = n0 + 3 * n1 + n4;
        a.base[6] = n0 + 3 * n1 + n4 + n5;
        int blocks = (int)((a.base[6] + 255) / 256);
        prep_kernel<<<blocks, 256>>>(a);
    }

    // launches 2-4: q/k/v projections (N=1152 -> 9 tiles of 128, exact)
    {
        dim3 grid(DP / 128, MROWS / 256, 1);   // (9,64)
        tc_gemm<1><<<grid, blk, SMEM_BYTES>>>(
            (const __nv_bfloat16*)p_xb, (const __nv_bfloat16*)p_Wq, p_q,
            DP, DP, DP, DP, DP, bq, DREAL, qscale, nullptr, 0, 0, 0);
        tc_gemm<1><<<grid, blk, SMEM_BYTES>>>(
            (const __nv_bfloat16*)p_xb, (const __nv_bfloat16*)p_Wk, p_k,
            DP, DP, DP, DP, DP, bk, DREAL, 1.0f, nullptr, 0, 0, 0);
        tc_gemm<1><<<grid, blk, SMEM_BYTES>>>(
            (const __nv_bfloat16*)p_xb, (const __nv_bfloat16*)p_Wv, p_v,
            DP, DP, DP, DP, DP, bv, DREAL, 1.0f, nullptr, 0, 0, 0);
    }

    // launch 5: scores, S = q @ k^T (scale folded into q), bf16 out
    {
        dim3 grid(NPOS / 128, NPOS / 256, NBATCH);  // (16,8,8)
        tc_gemm<4><<<grid, blk, SMEM_BYTES>>>(
            (const __nv_bfloat16*)p_q, (const __nv_bfloat16*)p_k, p_S,
            DP, DP, DP, NPOS, NPOS, nullptr, 0, 1.0f, nullptr,
            (size_t)NPOS * DP, (size_t)NPOS * DP, (size_t)NPOS * NPOS);
    }

    // launch 6: transpose V per batch (needs only v)
    {
        dim3 grid(NPOS / 32, DP / 32, NBATCH);
        transpose_kernel<<<grid, blk>>>((const __nv_bfloat16*)p_v,
                                        (__nv_bfloat16*)p_vt);
    }

    // launch 7: softmax rows
    softmax_kernel<<<NBATCH * NPOS, 256>>>((const __nv_bfloat16*)p_S,
                                           (__nv_bfloat16*)p_P);

    // attn = P @ Vt^T  (N=1152 -> 9 tiles, exact; vt has slack rows)
    {
        dim3 grid(DP / 128, NPOS / 256, NBATCH);  // (9,8,8)
        tc_gemm<4><<<grid, blk, SMEM_BYTES>>>(
            (const __nv_bfloat16*)p_P, (const __nv_bfloat16*)p_vt, p_attn,
            NPOS, NPOS, NPOS, DP, DP, nullptr, 0, 1.0f, nullptr,
            (size_t)NPOS * NPOS, (size_t)DP * NPOS, (size_t)NPOS * DP);
    }

    // h = gelu(attn @ We^T + be)  (N=4224 -> 33 tiles, exact)
    {
        dim3 grid(HP / 128, MROWS / 256, 1);   // (33,64)
        tc_gemm<2><<<grid, blk, SMEM_BYTES>>>(
            (const __nv_bfloat16*)p_attn, (const __nv_bfloat16*)p_We, p_h,
            DP, DP, DP, HP, HP, be, HREAL, 1.0f, nullptr, 0, 0, 0);
    }

    // out = h @ Wo^T + bo + x  (fp32; N=1028 -> 9 tiles, guarded)
    {
        dim3 grid((DREAL + 127) / 128, MROWS / 256, 1);  // (9,64)
        tc_gemm<3><<<grid, blk, SMEM_BYTES>>>(
            (const __nv_bfloat16*)p_h, (const __nv_bfloat16*)p_Wo, d_out,
            HP, HP, HP, DREAL, DREAL, bo, DREAL, 1.0f, x, 0, 0, 0);
    }
}